// round 6
// baseline (speedup 1.0000x reference)
#include <cuda_runtime.h>
#include <cuda_bf16.h>
#include <math.h>

// ---------------- problem constants ----------------
#define BATCH 64
#define HDIM  2048
#define SEQ   2048
#define NH    32
#define NKV   4
#define GQA   8          // NH/NKV
#define HD    128
#define NEXP  32
#define IDIM  768
#define TOPK  4
#define QKV_N 5120       // (NH+2*NKV)*HD
#define EPS   1e-6f

// ---------------- scratch (device globals) ----------------
// NOTE: any scratch passed as a kernel ARGUMENT must be resolved on the host
// via cudaGetSymbolAddress (host &g_x is the ATS-visible host shadow, NOT the
// device symbol — root cause of rounds 1-5). Device-side direct references
// (g_cnt, g_tok, g_act, ...) are correct as-is.
__device__ float g_hn   [BATCH * HDIM];
__device__ float g_qkv  [BATCH * QKV_N];
__device__ float g_attn [BATCH * NH * HD];
__device__ float g_hs2  [BATCH * HDIM];
__device__ float g_h2   [BATCH * HDIM];
__device__ float g_act  [NEXP * BATCH * IDIM];
__device__ float g_ypair[BATCH * TOPK * HDIM];
__device__ int   g_cnt  [NEXP];
__device__ int   g_tok  [NEXP * BATCH];
__device__ int   g_slot [NEXP * BATCH];
__device__ float g_wt   [NEXP * BATCH];

// ---------------- reset routing counters ----------------
__global__ void reset_k() {
    if (threadIdx.x < NEXP) g_cnt[threadIdx.x] = 0;
}

// ---------------- RMSNorm (block per token) ----------------
__global__ __launch_bounds__(256) void rmsnorm_k(
    const float* __restrict__ x, const float* __restrict__ w, float* __restrict__ y)
{
    int b = blockIdx.x, tid = threadIdx.x;
    const float* xb = x + b * HDIM;
    float s = 0.f;
    for (int i = tid; i < HDIM; i += 256) { float v = xb[i]; s += v * v; }
    for (int o = 16; o; o >>= 1) s += __shfl_xor_sync(0xffffffffu, s, o);
    __shared__ float red[8];
    __shared__ float inv;
    if ((tid & 31) == 0) red[tid >> 5] = s;
    __syncthreads();
    if (tid == 0) {
        float t = 0.f;
        #pragma unroll
        for (int i = 0; i < 8; i++) t += red[i];
        inv = rsqrtf(t * (1.f / HDIM) + EPS);
    }
    __syncthreads();
    float iv = inv;
    for (int i = tid; i < HDIM; i += 256) y[b * HDIM + i] = xb[i] * iv * w[i];
}

// ---------------- GEMM: C[64,N] = A[64,K] @ W[N,K]^T (+bias)(+res) ----------------
__global__ __launch_bounds__(256) void gemm64_nt(
    const float* __restrict__ A, const float* __restrict__ W,
    const float* __restrict__ bias, const float* __restrict__ res,
    float* __restrict__ C, int N, int K)
{
    __shared__ float As[32][72];
    __shared__ float Ws[32][33];
    int nb  = blockIdx.x * 32;
    int tid = threadIdx.x;
    int n = tid & 31, mg = tid >> 5;
    float acc[8] = {0,0,0,0,0,0,0,0};
    const float* wp = W + (long)nb * K;

    for (int k0 = 0; k0 < K; k0 += 32) {
        #pragma unroll
        for (int i = 0; i < 8; i++) {
            int x = tid + i * 256; int m = x >> 5, kk = x & 31;
            As[kk][m] = A[m * K + k0 + kk];
        }
        #pragma unroll
        for (int i = 0; i < 4; i++) {
            int x = tid + i * 256; int nn = x >> 5, kk = x & 31;
            Ws[nn][kk] = wp[(long)nn * K + k0 + kk];
        }
        __syncthreads();
        #pragma unroll
        for (int kk = 0; kk < 32; kk++) {
            float wv = Ws[n][kk];
            #pragma unroll
            for (int j = 0; j < 8; j++)
                acc[j] = fmaf(As[kk][mg * 8 + j], wv, acc[j]);
        }
        __syncthreads();
    }
    float bv = bias ? bias[nb + n] : 0.f;
    #pragma unroll
    for (int j = 0; j < 8; j++) {
        int m = mg * 8 + j;
        float o = acc[j] + bv;
        if (res) o += res[m * N + nb + n];
        C[(long)m * N + nb + n] = o;
    }
}

// ---------------- GQA flash-decode attention ----------------
__global__ __launch_bounds__(256) void attn_k(
    const float* __restrict__ kc, const float* __restrict__ vc,
    const int* __restrict__ seq_lens, float* __restrict__ out)
{
    int b  = blockIdx.x >> 2;
    int kv = blockIdx.x & 3;
    int tid = threadIdx.x, warp = tid >> 5, lane = tid & 31;
    int sl = seq_lens[b];
    if (sl < 0) sl = 0;
    if (sl > SEQ - 1) sl = SEQ - 1;
    int L  = sl + 1;
    const float scale = 0.08838834764831845f;  // 1/sqrt(128)

    const float* qbase = g_qkv + b * QKV_N + kv * GQA * HD;
    const float* knew  = g_qkv + b * QKV_N + NH * HD + kv * HD;
    const float* vnew  = g_qkv + b * QKV_N + (NH + NKV) * HD + kv * HD;

    float4 q[GQA];
    #pragma unroll
    for (int h = 0; h < GQA; h++) q[h] = *(const float4*)(qbase + h * HD + lane * 4);

    float m[GQA], l[GQA];
    float4 o[GQA];
    #pragma unroll
    for (int h = 0; h < GQA; h++) {
        m[h] = -INFINITY; l[h] = 0.f; o[h] = make_float4(0.f, 0.f, 0.f, 0.f);
    }

    for (int s = warp; s < L; s += 8) {
        const float* kp = (s == sl) ? knew : (kc + ((size_t)(b * SEQ + s) * NKV + kv) * HD);
        const float* vp = (s == sl) ? vnew : (vc + ((size_t)(b * SEQ + s) * NKV + kv) * HD);
        float4 kk = *(const float4*)(kp + lane * 4);
        float4 vv = *(const float4*)(vp + lane * 4);
        #pragma unroll
        for (int h = 0; h < GQA; h++) {
            float d = q[h].x * kk.x + q[h].y * kk.y + q[h].z * kk.z + q[h].w * kk.w;
            d += __shfl_xor_sync(0xffffffffu, d, 16);
            d += __shfl_xor_sync(0xffffffffu, d, 8);
            d += __shfl_xor_sync(0xffffffffu, d, 4);
            d += __shfl_xor_sync(0xffffffffu, d, 2);
            d += __shfl_xor_sync(0xffffffffu, d, 1);
            float sc = d * scale;
            float nm = fmaxf(m[h], sc);
            float corr = __expf(m[h] - nm);
            float p = __expf(sc - nm);
            l[h] = l[h] * corr + p;
            o[h].x = o[h].x * corr + p * vv.x;
            o[h].y = o[h].y * corr + p * vv.y;
            o[h].z = o[h].z * corr + p * vv.z;
            o[h].w = o[h].w * corr + p * vv.w;
            m[h] = nm;
        }
    }

    __shared__ float sm[8][GQA], sll[8][GQA];
    __shared__ float so[8][GQA][HD];
    #pragma unroll
    for (int h = 0; h < GQA; h++) {
        if (lane == 0) { sm[warp][h] = m[h]; sll[warp][h] = l[h]; }
        *(float4*)&so[warp][h][lane * 4] = o[h];
    }
    __syncthreads();

    for (int idx = tid; idx < GQA * HD; idx += 256) {
        int h = idx >> 7, d = idx & (HD - 1);
        float M = -INFINITY;
        #pragma unroll
        for (int w = 0; w < 8; w++) M = fmaxf(M, sm[w][h]);
        float acc = 0.f, Ls = 0.f;
        #pragma unroll
        for (int w = 0; w < 8; w++) {
            float c = __expf(sm[w][h] - M);
            acc += c * so[w][h][d];
            Ls  += c * sll[w][h];
        }
        out[b * NH * HD + (kv * GQA + h) * HD + d] = acc / Ls;
    }
}

// ---------------- gate: logits, top4, routing tables ----------------
__global__ __launch_bounds__(256) void gate_k(const float* __restrict__ gw)
{
    int b = blockIdx.x, tid = threadIdx.x, warp = tid >> 5, lane = tid & 31;
    __shared__ float lg[NEXP];
    const float* h = g_h2 + b * HDIM;
    for (int e = warp; e < NEXP; e += 8) {
        const float* g = gw + e * HDIM;
        float s = 0.f;
        for (int i = lane; i < HDIM; i += 32) s += h[i] * g[i];
        for (int o = 16; o; o >>= 1) s += __shfl_xor_sync(0xffffffffu, s, o);
        if (lane == 0) lg[e] = s;
    }
    __syncthreads();
    if (tid == 0) {
        float val[TOPK]; int idx[TOPK];
        unsigned used = 0;
        for (int j = 0; j < TOPK; j++) {
            float best = -1e30f; int bi = 0;
            for (int e = 0; e < NEXP; e++)
                if (!((used >> e) & 1u) && lg[e] > best) { best = lg[e]; bi = e; }
            used |= 1u << bi; val[j] = best; idx[j] = bi;
        }
        float s = 0.f, wj[TOPK];
        for (int j = 0; j < TOPK; j++) { wj[j] = expf(val[j] - val[0]); s += wj[j]; }
        float is = 1.f / s;
        for (int j = 0; j < TOPK; j++) {
            int e = idx[j];
            int pos = atomicAdd(&g_cnt[e], 1);
            g_tok [e * BATCH + pos] = b;
            g_slot[e * BATCH + pos] = j;
            g_wt  [e * BATCH + pos] = wj[j] * is;
        }
    }
}

// ---------------- MoE w1: act = silu(h2@Wg^T) * (h2@Wu^T) ----------------
__global__ __launch_bounds__(256) void moe_w1_k(const float* __restrict__ w1)
{
    int e = blockIdx.y;
    int cnt = g_cnt[e];
    int m0 = blockIdx.z * 16;
    if (m0 >= cnt) return;
    int ib = blockIdx.x * 32;
    __shared__ float As[32][18];
    __shared__ float Wg[32][33], Wu[32][33];
    __shared__ int toks[16];
    int tid = threadIdx.x;
    if (tid < 16) toks[tid] = (m0 + tid < cnt) ? g_tok[e * BATCH + m0 + tid]
                                               : g_tok[e * BATCH];
    __syncthreads();
    int n = tid & 31, mg = tid >> 5;
    float ag0 = 0.f, ag1 = 0.f, au0 = 0.f, au1 = 0.f;
    const float* w1g = w1 + ((long)e * 2 * IDIM + ib) * HDIM;
    const float* w1u = w1g + (long)IDIM * HDIM;

    for (int k0 = 0; k0 < HDIM; k0 += 32) {
        #pragma unroll
        for (int i = 0; i < 2; i++) {
            int x = tid + i * 256; int kk = x & 31, mm = x >> 5;
            As[kk][mm] = g_h2[toks[mm] * HDIM + k0 + kk];
        }
        #pragma unroll
        for (int i = 0; i < 4; i++) {
            int x = tid + i * 256; int nn = x >> 5, kk = x & 31;
            Wg[nn][kk] = w1g[(long)nn * HDIM + k0 + kk];
            Wu[nn][kk] = w1u[(long)nn * HDIM + k0 + kk];
        }
        __syncthreads();
        #pragma unroll
        for (int kk = 0; kk < 32; kk++) {
            float a0 = As[kk][mg * 2], a1 = As[kk][mg * 2 + 1];
            float gv = Wg[n][kk], uv = Wu[n][kk];
            ag0 = fmaf(a0, gv, ag0); ag1 = fmaf(a1, gv, ag1);
            au0 = fmaf(a0, uv, au0); au1 = fmaf(a1, uv, au1);
        }
        __syncthreads();
    }
    float gv[2] = {ag0, ag1}, uv[2] = {au0, au1};
    #pragma unroll
    for (int t = 0; t < 2; t++) {
        int m = m0 + mg * 2 + t;
        if (m < cnt) {
            float g = gv[t];
            float a = g / (1.f + expf(-g)) * uv[t];
            g_act[(e * BATCH + m) * IDIM + ib + n] = a;
        }
    }
}

// ---------------- MoE w2: y = act @ W2^T, weighted scatter ----------------
__global__ __launch_bounds__(256) void moe_w2_k(const float* __restrict__ w2)
{
    int e = blockIdx.y;
    int cnt = g_cnt[e];
    int m0 = blockIdx.z * 16;
    if (m0 >= cnt) return;
    int hb = blockIdx.x * 32;
    __shared__ float As[32][18];
    __shared__ float Ws[32][33];
    int tid = threadIdx.x;
    int n = tid & 31, mg = tid >> 5;
    float acc0 = 0.f, acc1 = 0.f;
    const float* wp = w2 + ((long)e * HDIM + hb) * IDIM;
    const float* ap = g_act + (e * BATCH + m0) * IDIM;

    for (int k0 = 0; k0 < IDIM; k0 += 32) {
        #pragma unroll
        for (int i = 0; i < 2; i++) {
            int x = tid + i * 256; int kk = x & 31, mm = x >> 5;
            As[kk][mm] = (m0 + mm < cnt) ? ap[mm * IDIM + k0 + kk] : 0.f;
        }
        #pragma unroll
        for (int i = 0; i < 4; i++) {
            int x = tid + i * 256; int nn = x >> 5, kk = x & 31;
            Ws[nn][kk] = wp[(long)nn * IDIM + k0 + kk];
        }
        __syncthreads();
        #pragma unroll
        for (int kk = 0; kk < 32; kk++) {
            float wv = Ws[n][kk];
            acc0 = fmaf(As[kk][mg * 2], wv, acc0);
            acc1 = fmaf(As[kk][mg * 2 + 1], wv, acc1);
        }
        __syncthreads();
    }
    float av[2] = {acc0, acc1};
    #pragma unroll
    for (int t = 0; t < 2; t++) {
        int m = m0 + mg * 2 + t;
        if (m < cnt) {
            int tok = g_tok [e * BATCH + m];
            int j   = g_slot[e * BATCH + m];
            float w = g_wt  [e * BATCH + m];
            g_ypair[(tok * TOPK + j) * HDIM + hb + n] = w * av[t];
        }
    }
}

// ---------------- finalize: out = hs2 + sum_j ypair ----------------
__global__ __launch_bounds__(256) void finalize_k(float* __restrict__ out)
{
    int idx = blockIdx.x * 256 + threadIdx.x;
    int tok = idx >> 11, hh = idx & (HDIM - 1);
    float s = g_hs2[idx];
    #pragma unroll
    for (int j = 0; j < TOPK; j++) s += g_ypair[(tok * TOPK + j) * HDIM + hh];
    out[idx] = s;
}

// ---------------- launch ----------------
extern "C" void kernel_launch(void* const* d_in, const int* in_sizes, int n_in,
                              void* d_out, int out_size)
{
    // Resolve REAL device addresses of scratch symbols once (host &g_x is the
    // host-side shadow — ATS makes it "work" by writing host RAM: rounds 1-5 bug).
    static float *p_hn = 0, *p_qkv = 0, *p_attn = 0, *p_hs2 = 0, *p_h2 = 0;
    if (!p_hn) {
        cudaGetSymbolAddress((void**)&p_hn,   g_hn);
        cudaGetSymbolAddress((void**)&p_qkv,  g_qkv);
        cudaGetSymbolAddress((void**)&p_attn, g_attn);
        cudaGetSymbolAddress((void**)&p_hs2,  g_hs2);
        cudaGetSymbolAddress((void**)&p_h2,   g_h2);
    }

    // Inputs: verified (round-5 diag) to arrive in setup_inputs dict order with
    // element counts; size matching kept as a safety net.
    const float *hidden = 0, *k_cache = 0, *v_cache = 0, *w_qkv = 0, *b_qkv = 0;
    const float *w_o = 0, *ln1_w = 0, *ln2_w = 0, *gate_w = 0, *w1 = 0, *w2 = 0;
    const int *positions = 0, *seqlens = 0;

    for (int i = 0; i < n_in; i++) {
        long sz = (long)in_sizes[i];
        const void* p = d_in[i];
        if      (sz == (long)BATCH * HDIM)            hidden = (const float*)p;
        else if (sz == (long)BATCH) {
            if (!positions) positions = (const int*)p; else seqlens = (const int*)p;
        }
        else if (sz == (long)BATCH * SEQ * NKV * HD) {
            if (!k_cache) k_cache = (const float*)p; else v_cache = (const float*)p;
        }
        else if (sz == (long)QKV_N * HDIM)            w_qkv  = (const float*)p;
        else if (sz == (long)QKV_N)                   b_qkv  = (const float*)p;
        else if (sz == (long)HDIM * NH * HD)          w_o    = (const float*)p;
        else if (sz == (long)HDIM) {
            if (!ln1_w) ln1_w = (const float*)p; else ln2_w = (const float*)p;
        }
        else if (sz == (long)NEXP * HDIM)             gate_w = (const float*)p;
        else if (sz == (long)NEXP * 2 * IDIM * HDIM)  w1     = (const float*)p;
        else if (sz == (long)NEXP * HDIM * IDIM)      w2     = (const float*)p;
    }
    if (!seqlens && positions) seqlens = positions;
    if (!v_cache) v_cache = k_cache;
    if (!ln2_w)   ln2_w   = ln1_w;

    float* out = (float*)d_out;

    reset_k<<<1, 32>>>();
    rmsnorm_k<<<BATCH, 256>>>(hidden, ln1_w, p_hn);
    gemm64_nt<<<QKV_N / 32, 256>>>(p_hn, w_qkv, b_qkv, nullptr, p_qkv, QKV_N, HDIM);
    attn_k<<<BATCH * NKV, 256>>>(k_cache, v_cache, seqlens, p_attn);
    gemm64_nt<<<HDIM / 32, 256>>>(p_attn, w_o, nullptr, hidden, p_hs2, HDIM, NH * HD);
    rmsnorm_k<<<BATCH, 256>>>(p_hs2, ln2_w, p_h2);
    gate_k<<<BATCH, 256>>>(gate_w);
    moe_w1_k<<<dim3(IDIM / 32, NEXP, 4), 256>>>(w1);
    moe_w2_k<<<dim3(HDIM / 32, NEXP, 4), 256>>>(w2);
    finalize_k<<<(BATCH * HDIM) / 256, 256>>>(out);
}

// round 7
// speedup vs baseline: 1.1264x; 1.1264x over previous
#include <cuda_runtime.h>
#include <cuda_bf16.h>
#include <math.h>

// ---------------- problem constants ----------------
#define BATCH 64
#define HDIM  2048
#define SEQ   2048
#define NH    32
#define NKV   4
#define GQA   8          // NH/NKV
#define HD    128
#define NEXP  32
#define IDIM  768
#define TOPK  4
#define QKV_N 5120       // (NH+2*NKV)*HD
#define EPS   1e-6f
#define SCHUNK 256
#define NCHUNK (SEQ / SCHUNK)   // 8

// ---------------- scratch (device globals) ----------------
// Scratch passed as kernel ARGUMENTS must be resolved via cudaGetSymbolAddress
// (host &g_x is the ATS host shadow — rounds 1-5 bug). In-kernel direct refs ok.
__device__ float g_hn   [BATCH * HDIM];
__device__ float g_qkv  [BATCH * QKV_N];
__device__ float g_attn [BATCH * NH * HD];
__device__ float g_hs2  [BATCH * HDIM];
__device__ float g_h2   [BATCH * HDIM];
__device__ float g_act  [NEXP * BATCH * IDIM];
__device__ float g_ypair[BATCH * TOPK * HDIM];
__device__ int   g_cnt  [NEXP];
__device__ int   g_tok  [NEXP * BATCH];
__device__ int   g_slot [NEXP * BATCH];
__device__ float g_wt   [NEXP * BATCH];
// split-S attention partials
__device__ float g_pm [BATCH * NKV * NCHUNK * GQA];
__device__ float g_pl [BATCH * NKV * NCHUNK * GQA];
__device__ float g_po [BATCH * NKV * NCHUNK * GQA * HD];   // 8 MB

// ---------------- reset routing counters ----------------
__global__ void reset_k() {
    if (threadIdx.x < NEXP) g_cnt[threadIdx.x] = 0;
}

// ---------------- RMSNorm (block per token) ----------------
__global__ __launch_bounds__(256) void rmsnorm_k(
    const float* __restrict__ x, const float* __restrict__ w, float* __restrict__ y)
{
    int b = blockIdx.x, tid = threadIdx.x;
    const float* xb = x + b * HDIM;
    float s = 0.f;
    for (int i = tid; i < HDIM; i += 256) { float v = xb[i]; s += v * v; }
    for (int o = 16; o; o >>= 1) s += __shfl_xor_sync(0xffffffffu, s, o);
    __shared__ float red[8];
    __shared__ float inv;
    if ((tid & 31) == 0) red[tid >> 5] = s;
    __syncthreads();
    if (tid == 0) {
        float t = 0.f;
        #pragma unroll
        for (int i = 0; i < 8; i++) t += red[i];
        inv = rsqrtf(t * (1.f / HDIM) + EPS);
    }
    __syncthreads();
    float iv = inv;
    for (int i = tid; i < HDIM; i += 256) y[b * HDIM + i] = xb[i] * iv * w[i];
}

// ---------------- GEMM: C[64,N] = A[64,K] @ W[N,K]^T (+bias)(+res) ----------------
__global__ __launch_bounds__(256) void gemm64_nt(
    const float* __restrict__ A, const float* __restrict__ W,
    const float* __restrict__ bias, const float* __restrict__ res,
    float* __restrict__ C, int N, int K)
{
    __shared__ float As[32][72];
    __shared__ float Ws[32][33];
    int nb  = blockIdx.x * 32;
    int tid = threadIdx.x;
    int n = tid & 31, mg = tid >> 5;
    float acc[8] = {0,0,0,0,0,0,0,0};
    const float* wp = W + (long)nb * K;

    for (int k0 = 0; k0 < K; k0 += 32) {
        #pragma unroll
        for (int i = 0; i < 8; i++) {
            int x = tid + i * 256; int m = x >> 5, kk = x & 31;
            As[kk][m] = A[m * K + k0 + kk];
        }
        #pragma unroll
        for (int i = 0; i < 4; i++) {
            int x = tid + i * 256; int nn = x >> 5, kk = x & 31;
            Ws[nn][kk] = wp[(long)nn * K + k0 + kk];
        }
        __syncthreads();
        #pragma unroll
        for (int kk = 0; kk < 32; kk++) {
            float wv = Ws[n][kk];
            float4 a0 = *(const float4*)&As[kk][mg * 8];
            float4 a1 = *(const float4*)&As[kk][mg * 8 + 4];
            acc[0] = fmaf(a0.x, wv, acc[0]); acc[1] = fmaf(a0.y, wv, acc[1]);
            acc[2] = fmaf(a0.z, wv, acc[2]); acc[3] = fmaf(a0.w, wv, acc[3]);
            acc[4] = fmaf(a1.x, wv, acc[4]); acc[5] = fmaf(a1.y, wv, acc[5]);
            acc[6] = fmaf(a1.z, wv, acc[6]); acc[7] = fmaf(a1.w, wv, acc[7]);
        }
        __syncthreads();
    }
    float bv = bias ? bias[nb + n] : 0.f;
    #pragma unroll
    for (int j = 0; j < 8; j++) {
        int m = mg * 8 + j;
        float o = acc[j] + bv;
        if (res) o += res[m * N + nb + n];
        C[(long)m * N + nb + n] = o;
    }
}

// ---------------- split-S GQA flash-decode: partial per (b, kv, chunk) ----------------
__global__ __launch_bounds__(256) void attn_part_k(
    const float* __restrict__ kc, const float* __restrict__ vc,
    const int* __restrict__ seq_lens)
{
    int c  = blockIdx.x;
    int kv = blockIdx.y;
    int b  = blockIdx.z;
    int tid = threadIdx.x, warp = tid >> 5, lane = tid & 31;
    int sl = seq_lens[b];
    if (sl < 0) sl = 0;
    if (sl > SEQ - 1) sl = SEQ - 1;
    int L  = sl + 1;
    int s0 = c * SCHUNK;
    if (s0 >= L) return;
    int s1 = s0 + SCHUNK; if (s1 > L) s1 = L;
    const float scale = 0.08838834764831845f;  // 1/sqrt(128)

    const float* qbase = g_qkv + b * QKV_N + kv * GQA * HD;
    const float* knew  = g_qkv + b * QKV_N + NH * HD + kv * HD;
    const float* vnew  = g_qkv + b * QKV_N + (NH + NKV) * HD + kv * HD;

    float4 q[GQA];
    #pragma unroll
    for (int h = 0; h < GQA; h++) q[h] = *(const float4*)(qbase + h * HD + lane * 4);

    float m[GQA], l[GQA];
    float4 o[GQA];
    #pragma unroll
    for (int h = 0; h < GQA; h++) {
        m[h] = -INFINITY; l[h] = 0.f; o[h] = make_float4(0.f, 0.f, 0.f, 0.f);
    }

    int s = s0 + warp;
    if (s < s1) {
        const float* kp = (s == sl) ? knew : (kc + ((size_t)(b * SEQ + s) * NKV + kv) * HD);
        const float* vp = (s == sl) ? vnew : (vc + ((size_t)(b * SEQ + s) * NKV + kv) * HD);
        float4 kk = *(const float4*)(kp + lane * 4);
        float4 vv = *(const float4*)(vp + lane * 4);
        for (;;) {
            int sn = s + 8;
            float4 knx, vnx;
            if (sn < s1) {   // prefetch next position (double MLP)
                const float* kp2 = (sn == sl) ? knew : (kc + ((size_t)(b * SEQ + sn) * NKV + kv) * HD);
                const float* vp2 = (sn == sl) ? vnew : (vc + ((size_t)(b * SEQ + sn) * NKV + kv) * HD);
                knx = *(const float4*)(kp2 + lane * 4);
                vnx = *(const float4*)(vp2 + lane * 4);
            }
            #pragma unroll
            for (int h = 0; h < GQA; h++) {
                float d = q[h].x * kk.x + q[h].y * kk.y + q[h].z * kk.z + q[h].w * kk.w;
                d += __shfl_xor_sync(0xffffffffu, d, 16);
                d += __shfl_xor_sync(0xffffffffu, d, 8);
                d += __shfl_xor_sync(0xffffffffu, d, 4);
                d += __shfl_xor_sync(0xffffffffu, d, 2);
                d += __shfl_xor_sync(0xffffffffu, d, 1);
                float sc = d * scale;
                float nm = fmaxf(m[h], sc);
                float corr = __expf(m[h] - nm);
                float p = __expf(sc - nm);
                l[h] = l[h] * corr + p;
                o[h].x = o[h].x * corr + p * vv.x;
                o[h].y = o[h].y * corr + p * vv.y;
                o[h].z = o[h].z * corr + p * vv.z;
                o[h].w = o[h].w * corr + p * vv.w;
                m[h] = nm;
            }
            if (sn >= s1) break;
            s = sn; kk = knx; vv = vnx;
        }
    }

    __shared__ float sm[8][GQA], sll[8][GQA];
    __shared__ float so[8][GQA][HD];
    #pragma unroll
    for (int h = 0; h < GQA; h++) {
        if (lane == 0) { sm[warp][h] = m[h]; sll[warp][h] = l[h]; }
        *(float4*)&so[warp][h][lane * 4] = o[h];
    }
    __syncthreads();

    int pbase = ((b * NKV + kv) * NCHUNK + c) * GQA;
    for (int idx = tid; idx < GQA * HD; idx += 256) {
        int h = idx >> 7, d = idx & (HD - 1);
        float M = -INFINITY;
        #pragma unroll
        for (int w = 0; w < 8; w++) M = fmaxf(M, sm[w][h]);
        float acc = 0.f, Ls = 0.f;
        #pragma unroll
        for (int w = 0; w < 8; w++) {
            float cw = __expf(sm[w][h] - M);
            acc += cw * so[w][h][d];
            Ls  += cw * sll[w][h];
        }
        g_po[(pbase + h) * HD + d] = acc;
        if (d == 0) { g_pm[pbase + h] = M; g_pl[pbase + h] = Ls; }
    }
}

// ---------------- combine split-S partials ----------------
__global__ __launch_bounds__(256) void attn_comb_k(
    const int* __restrict__ seq_lens, float* __restrict__ out)
{
    int b  = blockIdx.x >> 2;
    int kv = blockIdx.x & 3;
    int tid = threadIdx.x;
    int sl = seq_lens[b];
    if (sl < 0) sl = 0;
    if (sl > SEQ - 1) sl = SEQ - 1;
    int nch = sl / SCHUNK + 1;
    int base = (b * NKV + kv) * NCHUNK;

    for (int idx = tid; idx < GQA * HD; idx += 256) {
        int h = idx >> 7, d = idx & (HD - 1);
        float M = -INFINITY;
        for (int c = 0; c < nch; c++) M = fmaxf(M, g_pm[(base + c) * GQA + h]);
        float acc = 0.f, Ls = 0.f;
        for (int c = 0; c < nch; c++) {
            float w = __expf(g_pm[(base + c) * GQA + h] - M);
            acc += w * g_po[((base + c) * GQA + h) * HD + d];
            Ls  += w * g_pl[(base + c) * GQA + h];
        }
        out[b * NH * HD + (kv * GQA + h) * HD + d] = acc / Ls;
    }
}

// ---------------- gate: logits, top4, routing tables ----------------
__global__ __launch_bounds__(256) void gate_k(const float* __restrict__ gw)
{
    int b = blockIdx.x, tid = threadIdx.x, warp = tid >> 5, lane = tid & 31;
    __shared__ float lg[NEXP];
    const float* h = g_h2 + b * HDIM;
    for (int e = warp; e < NEXP; e += 8) {
        const float* g = gw + e * HDIM;
        float s = 0.f;
        for (int i = lane; i < HDIM; i += 32) s += h[i] * g[i];
        for (int o = 16; o; o >>= 1) s += __shfl_xor_sync(0xffffffffu, s, o);
        if (lane == 0) lg[e] = s;
    }
    __syncthreads();
    if (tid == 0) {
        float val[TOPK]; int idx[TOPK];
        unsigned used = 0;
        for (int j = 0; j < TOPK; j++) {
            float best = -1e30f; int bi = 0;
            for (int e = 0; e < NEXP; e++)
                if (!((used >> e) & 1u) && lg[e] > best) { best = lg[e]; bi = e; }
            used |= 1u << bi; val[j] = best; idx[j] = bi;
        }
        float s = 0.f, wj[TOPK];
        for (int j = 0; j < TOPK; j++) { wj[j] = expf(val[j] - val[0]); s += wj[j]; }
        float is = 1.f / s;
        for (int j = 0; j < TOPK; j++) {
            int e = idx[j];
            int pos = atomicAdd(&g_cnt[e], 1);
            g_tok [e * BATCH + pos] = b;
            g_slot[e * BATCH + pos] = j;
            g_wt  [e * BATCH + pos] = wj[j] * is;
        }
    }
}

// ---------------- MoE w1: act = silu(h2@Wg^T) * (h2@Wu^T) ----------------
__global__ __launch_bounds__(256) void moe_w1_k(const float* __restrict__ w1)
{
    int e = blockIdx.y;
    int cnt = g_cnt[e];
    int m0 = blockIdx.z * 16;
    if (m0 >= cnt) return;
    int ib = blockIdx.x * 32;
    __shared__ float As[32][18];
    __shared__ float Wg[32][33], Wu[32][33];
    __shared__ int toks[16];
    int tid = threadIdx.x;
    if (tid < 16) toks[tid] = (m0 + tid < cnt) ? g_tok[e * BATCH + m0 + tid]
                                               : g_tok[e * BATCH];
    __syncthreads();
    int n = tid & 31, mg = tid >> 5;
    float ag0 = 0.f, ag1 = 0.f, au0 = 0.f, au1 = 0.f;
    const float* w1g = w1 + ((long)e * 2 * IDIM + ib) * HDIM;
    const float* w1u = w1g + (long)IDIM * HDIM;

    for (int k0 = 0; k0 < HDIM; k0 += 32) {
        #pragma unroll
        for (int i = 0; i < 2; i++) {
            int x = tid + i * 256; int kk = x & 31, mm = x >> 5;
            As[kk][mm] = g_h2[toks[mm] * HDIM + k0 + kk];
        }
        #pragma unroll
        for (int i = 0; i < 4; i++) {
            int x = tid + i * 256; int nn = x >> 5, kk = x & 31;
            Wg[nn][kk] = w1g[(long)nn * HDIM + k0 + kk];
            Wu[nn][kk] = w1u[(long)nn * HDIM + k0 + kk];
        }
        __syncthreads();
        #pragma unroll
        for (int kk = 0; kk < 32; kk++) {
            float2 a = *(const float2*)&As[kk][mg * 2];
            float gv = Wg[n][kk], uv = Wu[n][kk];
            ag0 = fmaf(a.x, gv, ag0); ag1 = fmaf(a.y, gv, ag1);
            au0 = fmaf(a.x, uv, au0); au1 = fmaf(a.y, uv, au1);
        }
        __syncthreads();
    }
    float gv[2] = {ag0, ag1}, uv[2] = {au0, au1};
    #pragma unroll
    for (int t = 0; t < 2; t++) {
        int m = m0 + mg * 2 + t;
        if (m < cnt) {
            float g = gv[t];
            float a = g / (1.f + expf(-g)) * uv[t];
            g_act[(e * BATCH + m) * IDIM + ib + n] = a;
        }
    }
}

// ---------------- MoE w2: y = act @ W2^T, weighted scatter ----------------
__global__ __launch_bounds__(256) void moe_w2_k(const float* __restrict__ w2)
{
    int e = blockIdx.y;
    int cnt = g_cnt[e];
    int m0 = blockIdx.z * 16;
    if (m0 >= cnt) return;
    int hb = blockIdx.x * 32;
    __shared__ float As[32][18];
    __shared__ float Ws[32][33];
    int tid = threadIdx.x;
    int n = tid & 31, mg = tid >> 5;
    float acc0 = 0.f, acc1 = 0.f;
    const float* wp = w2 + ((long)e * HDIM + hb) * IDIM;
    const float* ap = g_act + (e * BATCH + m0) * IDIM;

    for (int k0 = 0; k0 < IDIM; k0 += 32) {
        #pragma unroll
        for (int i = 0; i < 2; i++) {
            int x = tid + i * 256; int kk = x & 31, mm = x >> 5;
            As[kk][mm] = (m0 + mm < cnt) ? ap[mm * IDIM + k0 + kk] : 0.f;
        }
        #pragma unroll
        for (int i = 0; i < 4; i++) {
            int x = tid + i * 256; int nn = x >> 5, kk = x & 31;
            Ws[nn][kk] = wp[(long)nn * IDIM + k0 + kk];
        }
        __syncthreads();
        #pragma unroll
        for (int kk = 0; kk < 32; kk++) {
            float2 a = *(const float2*)&As[kk][mg * 2];
            float wv = Ws[n][kk];
            acc0 = fmaf(a.x, wv, acc0);
            acc1 = fmaf(a.y, wv, acc1);
        }
        __syncthreads();
    }
    float av[2] = {acc0, acc1};
    #pragma unroll
    for (int t = 0; t < 2; t++) {
        int m = m0 + mg * 2 + t;
        if (m < cnt) {
            int tok = g_tok [e * BATCH + m];
            int j   = g_slot[e * BATCH + m];
            float w = g_wt  [e * BATCH + m];
            g_ypair[(tok * TOPK + j) * HDIM + hb + n] = w * av[t];
        }
    }
}

// ---------------- finalize: out = hs2 + sum_j ypair ----------------
__global__ __launch_bounds__(256) void finalize_k(float* __restrict__ out)
{
    int idx = blockIdx.x * 256 + threadIdx.x;
    int tok = idx >> 11, hh = idx & (HDIM - 1);
    float s = g_hs2[idx];
    #pragma unroll
    for (int j = 0; j < TOPK; j++) s += g_ypair[(tok * TOPK + j) * HDIM + hh];
    out[idx] = s;
}

// ---------------- launch ----------------
extern "C" void kernel_launch(void* const* d_in, const int* in_sizes, int n_in,
                              void* d_out, int out_size)
{
    static float *p_hn = 0, *p_qkv = 0, *p_attn = 0, *p_hs2 = 0, *p_h2 = 0;
    if (!p_hn) {
        cudaGetSymbolAddress((void**)&p_hn,   g_hn);
        cudaGetSymbolAddress((void**)&p_qkv,  g_qkv);
        cudaGetSymbolAddress((void**)&p_attn, g_attn);
        cudaGetSymbolAddress((void**)&p_hs2,  g_hs2);
        cudaGetSymbolAddress((void**)&p_h2,   g_h2);
    }

    const float *hidden = 0, *k_cache = 0, *v_cache = 0, *w_qkv = 0, *b_qkv = 0;
    const float *w_o = 0, *ln1_w = 0, *ln2_w = 0, *gate_w = 0, *w1 = 0, *w2 = 0;
    const int *positions = 0, *seqlens = 0;

    for (int i = 0; i < n_in; i++) {
        long sz = (long)in_sizes[i];
        const void* p = d_in[i];
        if      (sz == (long)BATCH * HDIM)            hidden = (const float*)p;
        else if (sz == (long)BATCH) {
            if (!positions) positions = (const int*)p; else seqlens = (const int*)p;
        }
        else if (sz == (long)BATCH * SEQ * NKV * HD) {
            if (!k_cache) k_cache = (const float*)p; else v_cache = (const float*)p;
        }
        else if (sz == (long)QKV_N * HDIM)            w_qkv  = (const float*)p;
        else if (sz == (long)QKV_N)                   b_qkv  = (const float*)p;
        else if (sz == (long)HDIM * NH * HD)          w_o    = (const float*)p;
        else if (sz == (long)HDIM) {
            if (!ln1_w) ln1_w = (const float*)p; else ln2_w = (const float*)p;
        }
        else if (sz == (long)NEXP * HDIM)             gate_w = (const float*)p;
        else if (sz == (long)NEXP * 2 * IDIM * HDIM)  w1     = (const float*)p;
        else if (sz == (long)NEXP * HDIM * IDIM)      w2     = (const float*)p;
    }
    if (!seqlens && positions) seqlens = positions;
    if (!v_cache) v_cache = k_cache;
    if (!ln2_w)   ln2_w   = ln1_w;

    float* out = (float*)d_out;

    reset_k<<<1, 32>>>();
    rmsnorm_k<<<BATCH, 256>>>(hidden, ln1_w, p_hn);
    gemm64_nt<<<QKV_N / 32, 256>>>(p_hn, w_qkv, b_qkv, nullptr, p_qkv, QKV_N, HDIM);
    attn_part_k<<<dim3(NCHUNK, NKV, BATCH), 256>>>(k_cache, v_cache, seqlens);
    attn_comb_k<<<BATCH * NKV, 256>>>(seqlens, p_attn);
    gemm64_nt<<<HDIM / 32, 256>>>(p_attn, w_o, nullptr, hidden, p_hs2, HDIM, NH * HD);
    rmsnorm_k<<<BATCH, 256>>>(p_hs2, ln2_w, p_h2);
    gate_k<<<BATCH, 256>>>(gate_w);
    moe_w1_k<<<dim3(IDIM / 32, NEXP, 4), 256>>>(w1);
    moe_w2_k<<<dim3(HDIM / 32, NEXP, 4), 256>>>(w2);
    finalize_k<<<(BATCH * HDIM) / 256, 256>>>(out);
}

// round 8
// speedup vs baseline: 1.1995x; 1.0650x over previous
#include <cuda_runtime.h>
#include <cuda_bf16.h>
#include <math.h>

// ---------------- problem constants ----------------
#define BATCH 64
#define HDIM  2048
#define SEQ   2048
#define NH    32
#define NKV   4
#define GQA   8          // NH/NKV
#define HD    128
#define NEXP  32
#define IDIM  768
#define TOPK  4
#define QKV_N 5120       // (NH+2*NKV)*HD
#define EPS   1e-6f
#define SCHUNK 256
#define NCHUNK (SEQ / SCHUNK)   // 8

// ---------------- scratch (device globals) ----------------
// Scratch passed as kernel ARGUMENTS must be resolved via cudaGetSymbolAddress
// (host &g_x is the ATS host shadow — rounds 1-5 bug). In-kernel refs ok.
__device__ float g_hn   [BATCH * HDIM];
__device__ float g_qkv  [BATCH * QKV_N];
__device__ float g_attn [BATCH * NH * HD];
__device__ float g_hs2  [BATCH * HDIM];
__device__ float g_h2   [BATCH * HDIM];
__device__ float g_act  [NEXP * BATCH * IDIM];
__device__ float g_ypair[BATCH * TOPK * HDIM];
__device__ float g_part [8 * BATCH * QKV_N / 2];   // K-split partials (covers 4x5120, 8x2048)
__device__ int   g_cnt  [NEXP];
__device__ int   g_tok  [NEXP * BATCH];
__device__ int   g_slot [NEXP * BATCH];
__device__ float g_wt   [NEXP * BATCH];
// split-S attention partials
__device__ float g_pm [BATCH * NKV * NCHUNK * GQA];
__device__ float g_pl [BATCH * NKV * NCHUNK * GQA];
__device__ float g_po [BATCH * NKV * NCHUNK * GQA * HD];

// ---------------- reset routing counters ----------------
__global__ void reset_k() {
    if (threadIdx.x < NEXP) g_cnt[threadIdx.x] = 0;
}

// ---------------- RMSNorm (block per token) ----------------
__global__ __launch_bounds__(256) void rmsnorm_k(
    const float* __restrict__ x, const float* __restrict__ w, float* __restrict__ y)
{
    int b = blockIdx.x, tid = threadIdx.x;
    const float* xb = x + b * HDIM;
    float s = 0.f;
    for (int i = tid; i < HDIM; i += 256) { float v = xb[i]; s += v * v; }
    for (int o = 16; o; o >>= 1) s += __shfl_xor_sync(0xffffffffu, s, o);
    __shared__ float red[8];
    __shared__ float inv;
    if ((tid & 31) == 0) red[tid >> 5] = s;
    __syncthreads();
    if (tid == 0) {
        float t = 0.f;
        #pragma unroll
        for (int i = 0; i < 8; i++) t += red[i];
        inv = rsqrtf(t * (1.f / HDIM) + EPS);
    }
    __syncthreads();
    float iv = inv;
    for (int i = tid; i < HDIM; i += 256) y[b * HDIM + i] = xb[i] * iv * w[i];
}

// ---------------- GEMM partial: part[ks][64][N] = A[64,Kslice] @ W[N,Kslice]^T ----
// BM=64, BN=64, BK=16, 256 thr, 4x4 register tile, double-buffered smem.
__global__ __launch_bounds__(256) void gemm_part_k(
    const float* __restrict__ A, const float* __restrict__ W,
    float* __restrict__ part, int N, int K, int ksplit)
{
    __shared__ float As[2][16][68];
    __shared__ float Ws[2][16][68];
    int nb = blockIdx.x * 64;
    int ks = blockIdx.y;
    int klen = K / ksplit;
    int kbeg = ks * klen;
    int tiles = klen / 16;
    int tid = threadIdx.x;

    int lm = tid >> 2;            // 0..63
    int lk = (tid & 3) * 4;       // 0,4,8,12
    const float* Ag = A + (long)lm * K + kbeg + lk;
    const float* Wg = W + (long)(nb + lm) * K + kbeg + lk;

    int tx = tid & 15, ty = tid >> 4;
    float acc[4][4] = {};

    float4 ra = *(const float4*)Ag;
    float4 rw = *(const float4*)Wg;
    As[0][lk+0][lm] = ra.x; As[0][lk+1][lm] = ra.y; As[0][lk+2][lm] = ra.z; As[0][lk+3][lm] = ra.w;
    Ws[0][lk+0][lm] = rw.x; Ws[0][lk+1][lm] = rw.y; Ws[0][lk+2][lm] = rw.z; Ws[0][lk+3][lm] = rw.w;
    __syncthreads();

    for (int t = 0; t < tiles; t++) {
        int cur = t & 1;
        if (t + 1 < tiles) {
            ra = *(const float4*)(Ag + (t + 1) * 16);
            rw = *(const float4*)(Wg + (t + 1) * 16);
        }
        #pragma unroll
        for (int kk = 0; kk < 16; kk++) {
            float4 a = *(const float4*)&As[cur][kk][ty * 4];
            float4 w = *(const float4*)&Ws[cur][kk][tx * 4];
            acc[0][0] = fmaf(a.x, w.x, acc[0][0]); acc[0][1] = fmaf(a.x, w.y, acc[0][1]);
            acc[0][2] = fmaf(a.x, w.z, acc[0][2]); acc[0][3] = fmaf(a.x, w.w, acc[0][3]);
            acc[1][0] = fmaf(a.y, w.x, acc[1][0]); acc[1][1] = fmaf(a.y, w.y, acc[1][1]);
            acc[1][2] = fmaf(a.y, w.z, acc[1][2]); acc[1][3] = fmaf(a.y, w.w, acc[1][3]);
            acc[2][0] = fmaf(a.z, w.x, acc[2][0]); acc[2][1] = fmaf(a.z, w.y, acc[2][1]);
            acc[2][2] = fmaf(a.z, w.z, acc[2][2]); acc[2][3] = fmaf(a.z, w.w, acc[2][3]);
            acc[3][0] = fmaf(a.w, w.x, acc[3][0]); acc[3][1] = fmaf(a.w, w.y, acc[3][1]);
            acc[3][2] = fmaf(a.w, w.z, acc[3][2]); acc[3][3] = fmaf(a.w, w.w, acc[3][3]);
        }
        __syncthreads();
        if (t + 1 < tiles) {
            int nxt = 1 - cur;
            As[nxt][lk+0][lm] = ra.x; As[nxt][lk+1][lm] = ra.y; As[nxt][lk+2][lm] = ra.z; As[nxt][lk+3][lm] = ra.w;
            Ws[nxt][lk+0][lm] = rw.x; Ws[nxt][lk+1][lm] = rw.y; Ws[nxt][lk+2][lm] = rw.z; Ws[nxt][lk+3][lm] = rw.w;
            __syncthreads();
        }
    }

    #pragma unroll
    for (int i = 0; i < 4; i++) {
        float4 v = make_float4(acc[i][0], acc[i][1], acc[i][2], acc[i][3]);
        *(float4*)&part[((long)(ks * 64 + ty * 4 + i)) * N + nb + tx * 4] = v;
    }
}

// ---------------- GEMM reduce: C = sum_ks part + bias (+res) ----------------
__global__ __launch_bounds__(256) void gemm_reduce_k(
    const float* __restrict__ part, const float* __restrict__ bias,
    const float* __restrict__ res, float* __restrict__ C, int N, int ksplit)
{
    int idx = (blockIdx.x * 256 + threadIdx.x) * 4;   // over 64*N
    int m = idx / N, n = idx % N;
    float4 s = bias ? *(const float4*)&bias[n] : make_float4(0.f, 0.f, 0.f, 0.f);
    for (int ks = 0; ks < ksplit; ks++) {
        float4 p = *(const float4*)&part[((long)(ks * 64 + m)) * N + n];
        s.x += p.x; s.y += p.y; s.z += p.z; s.w += p.w;
    }
    if (res) {
        float4 r = *(const float4*)&res[idx];
        s.x += r.x; s.y += r.y; s.z += r.z; s.w += r.w;
    }
    *(float4*)&C[idx] = s;
}

// ---------------- split-S GQA flash-decode: partial per (b, kv, chunk) ----------------
__global__ __launch_bounds__(256) void attn_part_k(
    const float* __restrict__ kc, const float* __restrict__ vc,
    const int* __restrict__ seq_lens)
{
    int c  = blockIdx.x;
    int kv = blockIdx.y;
    int b  = blockIdx.z;
    int tid = threadIdx.x, warp = tid >> 5, lane = tid & 31;
    int sl = seq_lens[b];
    if (sl < 0) sl = 0;
    if (sl > SEQ - 1) sl = SEQ - 1;
    int L  = sl + 1;
    int s0 = c * SCHUNK;
    if (s0 >= L) return;
    int s1 = s0 + SCHUNK; if (s1 > L) s1 = L;
    const float scale = 0.08838834764831845f;

    const float* qbase = g_qkv + b * QKV_N + kv * GQA * HD;
    const float* knew  = g_qkv + b * QKV_N + NH * HD + kv * HD;
    const float* vnew  = g_qkv + b * QKV_N + (NH + NKV) * HD + kv * HD;

    float4 q[GQA];
    #pragma unroll
    for (int h = 0; h < GQA; h++) q[h] = *(const float4*)(qbase + h * HD + lane * 4);

    float m[GQA], l[GQA];
    float4 o[GQA];
    #pragma unroll
    for (int h = 0; h < GQA; h++) {
        m[h] = -INFINITY; l[h] = 0.f; o[h] = make_float4(0.f, 0.f, 0.f, 0.f);
    }

    int s = s0 + warp;
    if (s < s1) {
        const float* kp = (s == sl) ? knew : (kc + ((size_t)(b * SEQ + s) * NKV + kv) * HD);
        const float* vp = (s == sl) ? vnew : (vc + ((size_t)(b * SEQ + s) * NKV + kv) * HD);
        float4 kk = *(const float4*)(kp + lane * 4);
        float4 vv = *(const float4*)(vp + lane * 4);
        for (;;) {
            int sn = s + 8;
            float4 knx, vnx;
            if (sn < s1) {
                const float* kp2 = (sn == sl) ? knew : (kc + ((size_t)(b * SEQ + sn) * NKV + kv) * HD);
                const float* vp2 = (sn == sl) ? vnew : (vc + ((size_t)(b * SEQ + sn) * NKV + kv) * HD);
                knx = *(const float4*)(kp2 + lane * 4);
                vnx = *(const float4*)(vp2 + lane * 4);
            }
            #pragma unroll
            for (int h = 0; h < GQA; h++) {
                float d = q[h].x * kk.x + q[h].y * kk.y + q[h].z * kk.z + q[h].w * kk.w;
                d += __shfl_xor_sync(0xffffffffu, d, 16);
                d += __shfl_xor_sync(0xffffffffu, d, 8);
                d += __shfl_xor_sync(0xffffffffu, d, 4);
                d += __shfl_xor_sync(0xffffffffu, d, 2);
                d += __shfl_xor_sync(0xffffffffu, d, 1);
                float sc = d * scale;
                float nm = fmaxf(m[h], sc);
                float corr = __expf(m[h] - nm);
                float p = __expf(sc - nm);
                l[h] = l[h] * corr + p;
                o[h].x = o[h].x * corr + p * vv.x;
                o[h].y = o[h].y * corr + p * vv.y;
                o[h].z = o[h].z * corr + p * vv.z;
                o[h].w = o[h].w * corr + p * vv.w;
                m[h] = nm;
            }
            if (sn >= s1) break;
            s = sn; kk = knx; vv = vnx;
        }
    }

    __shared__ float sm[8][GQA], sll[8][GQA];
    __shared__ float so[8][GQA][HD];
    #pragma unroll
    for (int h = 0; h < GQA; h++) {
        if (lane == 0) { sm[warp][h] = m[h]; sll[warp][h] = l[h]; }
        *(float4*)&so[warp][h][lane * 4] = o[h];
    }
    __syncthreads();

    int pbase = ((b * NKV + kv) * NCHUNK + c) * GQA;
    for (int idx = tid; idx < GQA * HD; idx += 256) {
        int h = idx >> 7, d = idx & (HD - 1);
        float M = -INFINITY;
        #pragma unroll
        for (int w = 0; w < 8; w++) M = fmaxf(M, sm[w][h]);
        float acc = 0.f, Ls = 0.f;
        #pragma unroll
        for (int w = 0; w < 8; w++) {
            float cw = __expf(sm[w][h] - M);
            acc += cw * so[w][h][d];
            Ls  += cw * sll[w][h];
        }
        g_po[(pbase + h) * HD + d] = acc;
        if (d == 0) { g_pm[pbase + h] = M; g_pl[pbase + h] = Ls; }
    }
}

// ---------------- combine split-S partials ----------------
__global__ __launch_bounds__(256) void attn_comb_k(
    const int* __restrict__ seq_lens, float* __restrict__ out)
{
    int b  = blockIdx.x >> 2;
    int kv = blockIdx.x & 3;
    int tid = threadIdx.x;
    int sl = seq_lens[b];
    if (sl < 0) sl = 0;
    if (sl > SEQ - 1) sl = SEQ - 1;
    int nch = sl / SCHUNK + 1;
    int base = (b * NKV + kv) * NCHUNK;

    for (int idx = tid; idx < GQA * HD; idx += 256) {
        int h = idx >> 7, d = idx & (HD - 1);
        float M = -INFINITY;
        for (int c = 0; c < nch; c++) M = fmaxf(M, g_pm[(base + c) * GQA + h]);
        float acc = 0.f, Ls = 0.f;
        for (int c = 0; c < nch; c++) {
            float w = __expf(g_pm[(base + c) * GQA + h] - M);
            acc += w * g_po[((base + c) * GQA + h) * HD + d];
            Ls  += w * g_pl[(base + c) * GQA + h];
        }
        out[b * NH * HD + (kv * GQA + h) * HD + d] = acc / Ls;
    }
}

// ---------------- gate: logits, top4, routing tables ----------------
__global__ __launch_bounds__(256) void gate_k(const float* __restrict__ gw)
{
    int b = blockIdx.x, tid = threadIdx.x, warp = tid >> 5, lane = tid & 31;
    __shared__ float lg[NEXP];
    const float* h = g_h2 + b * HDIM;
    for (int e = warp; e < NEXP; e += 8) {
        const float* g = gw + e * HDIM;
        float s = 0.f;
        for (int i = lane; i < HDIM; i += 32) s += h[i] * g[i];
        for (int o = 16; o; o >>= 1) s += __shfl_xor_sync(0xffffffffu, s, o);
        if (lane == 0) lg[e] = s;
    }
    __syncthreads();
    if (tid == 0) {
        float val[TOPK]; int idx[TOPK];
        unsigned used = 0;
        for (int j = 0; j < TOPK; j++) {
            float best = -1e30f; int bi = 0;
            for (int e = 0; e < NEXP; e++)
                if (!((used >> e) & 1u) && lg[e] > best) { best = lg[e]; bi = e; }
            used |= 1u << bi; val[j] = best; idx[j] = bi;
        }
        float s = 0.f, wj[TOPK];
        for (int j = 0; j < TOPK; j++) { wj[j] = expf(val[j] - val[0]); s += wj[j]; }
        float is = 1.f / s;
        for (int j = 0; j < TOPK; j++) {
            int e = idx[j];
            int pos = atomicAdd(&g_cnt[e], 1);
            g_tok [e * BATCH + pos] = b;
            g_slot[e * BATCH + pos] = j;
            g_wt  [e * BATCH + pos] = wj[j] * is;
        }
    }
}

// ---------------- MoE w1: BN=64, 1m x 4n x {g,u}, double-buffered ----------------
// grid (IDIM/64, NEXP, 4)
__global__ __launch_bounds__(256) void moe_w1_k(const float* __restrict__ w1)
{
    int e = blockIdx.y;
    int cnt = g_cnt[e];
    int m0 = blockIdx.z * 16;
    if (m0 >= cnt) return;
    int ib = blockIdx.x * 64;

    __shared__ float As[2][16][17];
    __shared__ float Gs[2][16][68];
    __shared__ float Us[2][16][68];
    __shared__ int toks[16];

    int tid = threadIdx.x;
    if (tid < 16) toks[tid] = (m0 + tid < cnt) ? g_tok[e * BATCH + m0 + tid]
                                               : g_tok[e * BATCH];
    __syncthreads();

    int am = tid >> 4, ak = tid & 15;            // A loader: 1 scalar
    int ln = tid >> 2, lk = (tid & 3) * 4;       // W loader: float4
    const float* Agp = g_h2 + (long)toks[am] * HDIM + ak;
    const float* Ggp = w1 + ((long)e * 2 * IDIM + ib + ln) * HDIM + lk;
    const float* Ugp = Ggp + (long)IDIM * HDIM;

    int tx = tid & 15, ty = tid >> 4;
    float ag[4] = {}, au[4] = {};

    float raa = *Agp;
    float4 rg = *(const float4*)Ggp;
    float4 ru = *(const float4*)Ugp;
    As[0][ak][am] = raa;
    Gs[0][lk+0][ln] = rg.x; Gs[0][lk+1][ln] = rg.y; Gs[0][lk+2][ln] = rg.z; Gs[0][lk+3][ln] = rg.w;
    Us[0][lk+0][ln] = ru.x; Us[0][lk+1][ln] = ru.y; Us[0][lk+2][ln] = ru.z; Us[0][lk+3][ln] = ru.w;
    __syncthreads();

    const int tiles = HDIM / 16;
    for (int t = 0; t < tiles; t++) {
        int cur = t & 1;
        if (t + 1 < tiles) {
            raa = *(Agp + (t + 1) * 16);
            rg  = *(const float4*)(Ggp + (t + 1) * 16);
            ru  = *(const float4*)(Ugp + (t + 1) * 16);
        }
        #pragma unroll
        for (int kk = 0; kk < 16; kk++) {
            float a = As[cur][kk][ty];
            float4 g4 = *(const float4*)&Gs[cur][kk][tx * 4];
            float4 u4 = *(const float4*)&Us[cur][kk][tx * 4];
            ag[0] = fmaf(a, g4.x, ag[0]); ag[1] = fmaf(a, g4.y, ag[1]);
            ag[2] = fmaf(a, g4.z, ag[2]); ag[3] = fmaf(a, g4.w, ag[3]);
            au[0] = fmaf(a, u4.x, au[0]); au[1] = fmaf(a, u4.y, au[1]);
            au[2] = fmaf(a, u4.z, au[2]); au[3] = fmaf(a, u4.w, au[3]);
        }
        __syncthreads();
        if (t + 1 < tiles) {
            int nxt = 1 - cur;
            As[nxt][ak][am] = raa;
            Gs[nxt][lk+0][ln] = rg.x; Gs[nxt][lk+1][ln] = rg.y; Gs[nxt][lk+2][ln] = rg.z; Gs[nxt][lk+3][ln] = rg.w;
            Us[nxt][lk+0][ln] = ru.x; Us[nxt][lk+1][ln] = ru.y; Us[nxt][lk+2][ln] = ru.z; Us[nxt][lk+3][ln] = ru.w;
            __syncthreads();
        }
    }

    int m = m0 + ty;
    if (m < cnt) {
        float4 v;
        float* vp = (float*)&v;
        #pragma unroll
        for (int j = 0; j < 4; j++) {
            float g = ag[j];
            vp[j] = g / (1.f + expf(-g)) * au[j];
        }
        *(float4*)&g_act[(long)(e * BATCH + m) * IDIM + ib + tx * 4] = v;
    }
}

// ---------------- MoE w2: BN=64, 1m x 4n, double-buffered ----------------
// grid (HDIM/64, NEXP, 4)
__global__ __launch_bounds__(256) void moe_w2_k(const float* __restrict__ w2)
{
    int e = blockIdx.y;
    int cnt = g_cnt[e];
    int m0 = blockIdx.z * 16;
    if (m0 >= cnt) return;
    int hb = blockIdx.x * 64;

    __shared__ float As[2][16][17];
    __shared__ float Ws[2][16][68];

    int tid = threadIdx.x;
    int am = tid >> 4, ak = tid & 15;
    int ln = tid >> 2, lk = (tid & 3) * 4;
    const float* Agp = g_act + (long)(e * BATCH + m0 + am) * IDIM + ak;
    const float* Wgp = w2 + ((long)e * HDIM + hb + ln) * IDIM + lk;

    int tx = tid & 15, ty = tid >> 4;
    float acc[4] = {};

    float raa = *Agp;
    float4 rw = *(const float4*)Wgp;
    As[0][ak][am] = raa;
    Ws[0][lk+0][ln] = rw.x; Ws[0][lk+1][ln] = rw.y; Ws[0][lk+2][ln] = rw.z; Ws[0][lk+3][ln] = rw.w;
    __syncthreads();

    const int tiles = IDIM / 16;
    for (int t = 0; t < tiles; t++) {
        int cur = t & 1;
        if (t + 1 < tiles) {
            raa = *(Agp + (t + 1) * 16);
            rw  = *(const float4*)(Wgp + (t + 1) * 16);
        }
        #pragma unroll
        for (int kk = 0; kk < 16; kk++) {
            float a = As[cur][kk][ty];
            float4 w4 = *(const float4*)&Ws[cur][kk][tx * 4];
            acc[0] = fmaf(a, w4.x, acc[0]); acc[1] = fmaf(a, w4.y, acc[1]);
            acc[2] = fmaf(a, w4.z, acc[2]); acc[3] = fmaf(a, w4.w, acc[3]);
        }
        __syncthreads();
        if (t + 1 < tiles) {
            int nxt = 1 - cur;
            As[nxt][ak][am] = raa;
            Ws[nxt][lk+0][ln] = rw.x; Ws[nxt][lk+1][ln] = rw.y; Ws[nxt][lk+2][ln] = rw.z; Ws[nxt][lk+3][ln] = rw.w;
            __syncthreads();
        }
    }

    int m = m0 + ty;
    if (m < cnt) {
        int tok = g_tok [e * BATCH + m];
        int j   = g_slot[e * BATCH + m];
        float w = g_wt  [e * BATCH + m];
        float4 v = make_float4(w * acc[0], w * acc[1], w * acc[2], w * acc[3]);
        *(float4*)&g_ypair[(long)(tok * TOPK + j) * HDIM + hb + tx * 4] = v;
    }
}

// ---------------- finalize: out = hs2 + sum_j ypair ----------------
__global__ __launch_bounds__(256) void finalize_k(float* __restrict__ out)
{
    int idx = blockIdx.x * 256 + threadIdx.x;
    int tok = idx >> 11, hh = idx & (HDIM - 1);
    float s = g_hs2[idx];
    #pragma unroll
    for (int j = 0; j < TOPK; j++) s += g_ypair[(tok * TOPK + j) * HDIM + hh];
    out[idx] = s;
}

// ---------------- launch ----------------
extern "C" void kernel_launch(void* const* d_in, const int* in_sizes, int n_in,
                              void* d_out, int out_size)
{
    static float *p_hn = 0, *p_qkv = 0, *p_attn = 0, *p_hs2 = 0, *p_h2 = 0, *p_part = 0;
    if (!p_hn) {
        cudaGetSymbolAddress((void**)&p_hn,   g_hn);
        cudaGetSymbolAddress((void**)&p_qkv,  g_qkv);
        cudaGetSymbolAddress((void**)&p_attn, g_attn);
        cudaGetSymbolAddress((void**)&p_hs2,  g_hs2);
        cudaGetSymbolAddress((void**)&p_h2,   g_h2);
        cudaGetSymbolAddress((void**)&p_part, g_part);
    }

    const float *hidden = 0, *k_cache = 0, *v_cache = 0, *w_qkv = 0, *b_qkv = 0;
    const float *w_o = 0, *ln1_w = 0, *ln2_w = 0, *gate_w = 0, *w1 = 0, *w2 = 0;
    const int *positions = 0, *seqlens = 0;

    for (int i = 0; i < n_in; i++) {
        long sz = (long)in_sizes[i];
        const void* p = d_in[i];
        if      (sz == (long)BATCH * HDIM)            hidden = (const float*)p;
        else if (sz == (long)BATCH) {
            if (!positions) positions = (const int*)p; else seqlens = (const int*)p;
        }
        else if (sz == (long)BATCH * SEQ * NKV * HD) {
            if (!k_cache) k_cache = (const float*)p; else v_cache = (const float*)p;
        }
        else if (sz == (long)QKV_N * HDIM)            w_qkv  = (const float*)p;
        else if (sz == (long)QKV_N)                   b_qkv  = (const float*)p;
        else if (sz == (long)HDIM * NH * HD)          w_o    = (const float*)p;
        else if (sz == (long)HDIM) {
            if (!ln1_w) ln1_w = (const float*)p; else ln2_w = (const float*)p;
        }
        else if (sz == (long)NEXP * HDIM)             gate_w = (const float*)p;
        else if (sz == (long)NEXP * 2 * IDIM * HDIM)  w1     = (const float*)p;
        else if (sz == (long)NEXP * HDIM * IDIM)      w2     = (const float*)p;
    }
    if (!seqlens && positions) seqlens = positions;
    if (!v_cache) v_cache = k_cache;
    if (!ln2_w)   ln2_w   = ln1_w;

    float* out = (float*)d_out;

    reset_k<<<1, 32>>>();
    rmsnorm_k<<<BATCH, 256>>>(hidden, ln1_w, p_hn);
    // QKV: [64,5120] = hn @ w_qkv^T, K=2048 split 4
    gemm_part_k<<<dim3(QKV_N / 64, 4), 256>>>(p_hn, w_qkv, p_part, QKV_N, HDIM, 4);
    gemm_reduce_k<<<(64 * QKV_N) / 1024, 256>>>(p_part, b_qkv, nullptr, p_qkv, QKV_N, 4);
    attn_part_k<<<dim3(NCHUNK, NKV, BATCH), 256>>>(k_cache, v_cache, seqlens);
    attn_comb_k<<<BATCH * NKV, 256>>>(seqlens, p_attn);
    // O: [64,2048] = attn @ w_o^T + hidden, K=4096 split 8
    gemm_part_k<<<dim3(HDIM / 64, 8), 256>>>(p_attn, w_o, p_part, HDIM, NH * HD, 8);
    gemm_reduce_k<<<(64 * HDIM) / 1024, 256>>>(p_part, nullptr, hidden, p_hs2, HDIM, 8);
    rmsnorm_k<<<BATCH, 256>>>(p_hs2, ln2_w, p_h2);
    gate_k<<<BATCH, 256>>>(gate_w);
    moe_w1_k<<<dim3(IDIM / 64, NEXP, 4), 256>>>(w1);
    moe_w2_k<<<dim3(HDIM / 64, NEXP, 4), 256>>>(w2);
    finalize_k<<<(BATCH * HDIM) / 256, 256>>>(out);
}